// round 5
// baseline (speedup 1.0000x reference)
#include <cuda_runtime.h>
#include <cuda_bf16.h>
#include <cstdint>

#define GG   8
#define KK   1024
#define DD   64
#define BB   16
#define TS   4000
#define CF   512
#define TT   128        // tokens per CTA
#define NC   128        // codes per chunk
#define NCH  8
#define NTH  128
#define PTH  256

// ---------------- device globals ----------------
__device__ float g_e2[GG * KK];
__device__ unsigned int g_e2max[GG];
__device__ __align__(16) __nv_bfloat16 g_cbh[GG * KK * DD];
__device__ __align__(16) __nv_bfloat16 g_cbl[GG * KK * DD];

// ---------------- smem layout (bytes) ----------------
#define OFF_XS    0        // 32768: fp32 x tile [64][128]
#define OFF_AH    32768    // 16384: A hi bf16 SW128 (128 rows x 128B)
#define OFF_AL    49152    // 16384: A lo
#define OFF_BH    65536    // 16384: B hi chunk (128 codes x 128B)
#define OFF_BL    81920    // 16384: B lo
#define OFF_E2S   98304    // 4096
#define OFF_X2S   102400   // 512
#define OFF_BIX   102912   // 512
#define OFF_P1V   103424   // 1024: [2][128] min1
#define OFF_P1I   104448   // 1024: [2][128] idx1
#define OFF_P2V   105472   // 1024: [2][128] min2
#define OFF_FLG   106496   // 520 (count + 128 ids)
#define SMEM_BYTES 107024

#define SW128(o) ((o) ^ (((o) >> 3) & 0x70))

__device__ __forceinline__ uint32_t smem_u32(const void* p) {
    uint32_t a;
    asm("{ .reg .u64 t; cvta.to.shared.u64 t, %1; cvt.u32.u64 %0, t; }" : "=r"(a) : "l"(p));
    return a;
}

#define LDMX4(r0, r1, r2, r3, a) \
    asm volatile("ldmatrix.sync.aligned.m8n8.x4.shared.b16 {%0,%1,%2,%3}, [%4];" \
        : "=r"(r0), "=r"(r1), "=r"(r2), "=r"(r3) : "r"(a))

#define MMA16816(c0, c1, c2, c3, a0, a1, a2, a3, b0, b1) \
    asm volatile("mma.sync.aligned.m16n8k16.row.col.f32.bf16.bf16.f32 " \
        "{%0,%1,%2,%3}, {%4,%5,%6,%7}, {%8,%9}, {%0,%1,%2,%3};" \
        : "+f"(c0), "+f"(c1), "+f"(c2), "+f"(c3) \
        : "r"(a0), "r"(a1), "r"(a2), "r"(a3), "r"(b0), "r"(b1))

// ---------------- prep: bf16 split codebook + e2 + e2max ----------------
__global__ void prep_kernel(const float* __restrict__ cb) {
    int r = blockIdx.x * blockDim.x + threadIdx.x;
    if (r < GG * KK) {
        const float* row = cb + (size_t)r * DD;
        float s = 0.f;
        #pragma unroll
        for (int d = 0; d < DD; ++d) {
            float v = row[d];
            s = fmaf(v, v, s);
            __nv_bfloat16 h = __float2bfloat16(v);
            g_cbh[(size_t)r * DD + d] = h;
            g_cbl[(size_t)r * DD + d] = __float2bfloat16(v - __bfloat162float(h));
        }
        g_e2[r] = s;
        atomicMax(&g_e2max[r / KK], __float_as_uint(s));
    }
}

__global__ __launch_bounds__(NTH, 2)
void vq_main(const float* __restrict__ x, const float* __restrict__ cbf,
             float* __restrict__ out, int two_copies) {
    extern __shared__ char smem[];
    const uint32_t base = smem_u32(smem);
    float* xs  = (float*)(smem + OFF_XS);
    float* e2s = (float*)(smem + OFF_E2S);
    float* x2s = (float*)(smem + OFF_X2S);
    int*   bix = (int*)  (smem + OFF_BIX);
    float* p1v = (float*)(smem + OFF_P1V);
    int*   p1i = (int*)  (smem + OFF_P1I);
    float* p2v = (float*)(smem + OFF_P2V);
    int*   flg = (int*)  (smem + OFF_FLG);

    const int tid = threadIdx.x;
    const int wid = tid >> 5;
    const int lane = tid & 31;

    const int tile = blockIdx.x & 31;
    const int b = (blockIdx.x >> 5) & 15;
    const int g = blockIdx.x >> 9;
    const int t0 = tile * TT;
    const int nt = min(TT, TS - t0);

    if (tid == 0) flg[0] = 0;

    // ---- load x tile fp32 (zero-padded) ----
    const float* xb = x + ((size_t)(b * CF + g * DD)) * TS + t0;
    if (nt == TT) {
        #pragma unroll
        for (int i = tid; i < DD * (TT / 4); i += NTH) {
            int dd = i >> 5, tq = i & 31;
            float4 v = *(const float4*)(xb + (size_t)dd * TS + tq * 4);
            *(float4*)&xs[dd * TT + tq * 4] = v;
        }
    } else {
        for (int i = tid; i < DD * TT; i += NTH) {
            int dd = i / TT, tt = i % TT;
            xs[dd * TT + tt] = (tt < nt) ? xb[(size_t)dd * TS + tt] : 0.f;
        }
    }
    for (int i = tid; i < KK; i += NTH) e2s[i] = g_e2[g * KK + i];
    __syncthreads();

    // ---- build A hi/lo (SW128 rows of 128B) + x2; thread t = token t ----
    {
        float s = 0.f;
        #pragma unroll
        for (int q = 0; q < 8; ++q) {
            uint32_t hp[4], lp[4];
            #pragma unroll
            for (int pr = 0; pr < 4; ++pr) {
                float v0 = xs[(q * 8 + pr * 2) * TT + tid];
                float v1 = xs[(q * 8 + pr * 2 + 1) * TT + tid];
                s = fmaf(v0, v0, s);
                s = fmaf(v1, v1, s);
                __nv_bfloat16 h0 = __float2bfloat16(v0), h1 = __float2bfloat16(v1);
                __nv_bfloat16 l0 = __float2bfloat16(v0 - __bfloat162float(h0));
                __nv_bfloat16 l1 = __float2bfloat16(v1 - __bfloat162float(h1));
                hp[pr] = ((uint32_t)__bfloat16_as_ushort(h1) << 16) | __bfloat16_as_ushort(h0);
                lp[pr] = ((uint32_t)__bfloat16_as_ushort(l1) << 16) | __bfloat16_as_ushort(l0);
            }
            uint32_t off = SW128((uint32_t)(tid * 128 + q * 16));
            asm volatile("st.shared.v4.b32 [%0], {%1,%2,%3,%4};"
                :: "r"(base + OFF_AH + off), "r"(hp[0]), "r"(hp[1]), "r"(hp[2]), "r"(hp[3]) : "memory");
            asm volatile("st.shared.v4.b32 [%0], {%1,%2,%3,%4};"
                :: "r"(base + OFF_AL + off), "r"(lp[0]), "r"(lp[1]), "r"(lp[2]), "r"(lp[3]) : "memory");
        }
        x2s[tid] = s;
    }
    __syncthreads();

    // ---- warp tiling: 64 tokens x 64 codes per warp ----
    const int m0 = (wid >> 1) * 64;       // token base
    const int n0 = (wid & 1) * 64;        // code base within chunk (code half)
    const int half = wid & 1;
    const int gq = lane >> 2;             // 0..7
    const int t4 = lane & 3;              // 0..3

    const uint32_t aRow = (uint32_t)(m0 + (lane & 15));
    const uint32_t aCs = (uint32_t)(lane >> 4);
    const uint32_t bRow = (uint32_t)(n0 + (lane & 7) + ((lane >> 4) << 3));
    const uint32_t bCs = (uint32_t)((lane >> 3) & 1);

    uint32_t aB[4], aS[4], bB[4], bS[4];
    #pragma unroll
    for (int mt = 0; mt < 4; ++mt) {
        uint32_t r = aRow + 16u * mt;
        aB[mt] = base + OFF_AH + r * 128u;
        aS[mt] = r & 7u;
    }
    #pragma unroll
    for (int np = 0; np < 4; ++np) {
        uint32_t r = bRow + 16u * np;
        bB[np] = base + OFF_BH + r * 128u;
        bS[np] = r & 7u;
    }

    float x2r[4][2];
    #pragma unroll
    for (int mt = 0; mt < 4; ++mt) {
        x2r[mt][0] = x2s[m0 + 16 * mt + gq];
        x2r[mt][1] = x2s[m0 + 16 * mt + gq + 8];
    }

    const float INF = __int_as_float(0x7f800000);
    float m1[8], m2[8];
    int i1[8];
    #pragma unroll
    for (int r = 0; r < 8; ++r) { m1[r] = INF; m2[r] = INF; i1[r] = 0; }

    const __nv_bfloat16* cbh = g_cbh + (size_t)g * KK * DD;
    const __nv_bfloat16* cbl = g_cbl + (size_t)g * KK * DD;

    for (int c = 0; c < NCH; ++c) {
        // ---- load B chunk hi/lo into SW128 smem ----
        {
            const float4* sh = (const float4*)((const char*)cbh + (size_t)c * NC * DD * 2);
            const float4* sl = (const float4*)((const char*)cbl + (size_t)c * NC * DD * 2);
            #pragma unroll
            for (int i = tid; i < 1024; i += NTH) {
                uint32_t d = SW128((uint32_t)(i * 16));
                *(float4*)(smem + OFF_BH + d) = __ldg(sh + i);
                *(float4*)(smem + OFF_BL + d) = __ldg(sl + i);
            }
        }
        __syncthreads();

        float acc[4][8][4];
        #pragma unroll
        for (int mt = 0; mt < 4; ++mt)
            #pragma unroll
            for (int ntl = 0; ntl < 8; ++ntl)
                #pragma unroll
                for (int f = 0; f < 4; ++f) acc[mt][ntl][f] = 0.f;

        #pragma unroll
        for (int p = 0; p < 3; ++p) {
            const uint32_t aOff = (p == 2) ? 16384u : 0u;   // A: hi,hi,lo
            const uint32_t bOff = (p == 1) ? 16384u : 0u;   // B: hi,lo,hi
            #pragma unroll
            for (int ks = 0; ks < 4; ++ks) {
                uint32_t af[4][4];
                #pragma unroll
                for (int mt = 0; mt < 4; ++mt) {
                    uint32_t addr = aB[mt] + aOff + ((((uint32_t)(ks * 2) + aCs) ^ aS[mt]) << 4);
                    LDMX4(af[mt][0], af[mt][1], af[mt][2], af[mt][3], addr);
                }
                uint32_t bf[8][2];
                #pragma unroll
                for (int np = 0; np < 4; ++np) {
                    uint32_t addr = bB[np] + bOff + ((((uint32_t)(ks * 2) + bCs) ^ bS[np]) << 4);
                    LDMX4(bf[np * 2][0], bf[np * 2][1], bf[np * 2 + 1][0], bf[np * 2 + 1][1], addr);
                }
                #pragma unroll
                for (int mt = 0; mt < 4; ++mt)
                    #pragma unroll
                    for (int ntl = 0; ntl < 8; ++ntl)
                        MMA16816(acc[mt][ntl][0], acc[mt][ntl][1], acc[mt][ntl][2], acc[mt][ntl][3],
                                 af[mt][0], af[mt][1], af[mt][2], af[mt][3],
                                 bf[ntl][0], bf[ntl][1]);
            }
        }

        // ---- argmin epilogue on register accumulators ----
        #pragma unroll
        for (int ntl = 0; ntl < 8; ++ntl) {
            int k = c * NC + n0 + 8 * ntl + 2 * t4;
            float2 e2p = *(const float2*)&e2s[k];
            #pragma unroll
            for (int mt = 0; mt < 4; ++mt) {
                float d00 = fmaf(acc[mt][ntl][0], -2.f, x2r[mt][0]) + e2p.x;
                float d01 = fmaf(acc[mt][ntl][1], -2.f, x2r[mt][0]) + e2p.y;
                float d10 = fmaf(acc[mt][ntl][2], -2.f, x2r[mt][1]) + e2p.x;
                float d11 = fmaf(acc[mt][ntl][3], -2.f, x2r[mt][1]) + e2p.y;
                int r0 = mt * 2, r1 = mt * 2 + 1;
                if (d00 < m1[r0]) { m2[r0] = m1[r0]; m1[r0] = d00; i1[r0] = k; }
                else if (d00 < m2[r0]) m2[r0] = d00;
                if (d01 < m1[r0]) { m2[r0] = m1[r0]; m1[r0] = d01; i1[r0] = k + 1; }
                else if (d01 < m2[r0]) m2[r0] = d01;
                if (d10 < m1[r1]) { m2[r1] = m1[r1]; m1[r1] = d10; i1[r1] = k; }
                else if (d10 < m2[r1]) m2[r1] = d10;
                if (d11 < m1[r1]) { m2[r1] = m1[r1]; m1[r1] = d11; i1[r1] = k + 1; }
                else if (d11 < m2[r1]) m2[r1] = d11;
            }
        }
        __syncthreads();
    }

    // ---- quad reduce (lanes t4=0..3 share each row) ----
    #pragma unroll
    for (int r = 0; r < 8; ++r) {
        #pragma unroll
        for (int o = 1; o <= 2; o <<= 1) {
            float om1 = __shfl_xor_sync(0xffffffffu, m1[r], o);
            float om2 = __shfl_xor_sync(0xffffffffu, m2[r], o);
            int   oi  = __shfl_xor_sync(0xffffffffu, i1[r], o);
            if (om1 < m1[r] || (om1 == m1[r] && oi < i1[r])) {
                m2[r] = fminf(m1[r], om2); m1[r] = om1; i1[r] = oi;
            } else {
                m2[r] = fminf(m2[r], om1);
            }
        }
    }

    // ---- stage per-code-half partials, then merge across halves ----
    if (t4 == 0) {
        #pragma unroll
        for (int mt = 0; mt < 4; ++mt)
            #pragma unroll
            for (int h = 0; h < 2; ++h) {
                int r = mt * 2 + h;
                int tok = m0 + 16 * mt + 8 * h + gq;
                p1v[half * TT + tok] = m1[r];
                p1i[half * TT + tok] = i1[r];
                p2v[half * TT + tok] = m2[r];
            }
    }
    __syncthreads();

    const float e2m = __uint_as_float(g_e2max[g]);
    if (tid < TT) {
        float av = p1v[tid], a2 = p2v[tid]; int ai = p1i[tid];
        float bv = p1v[TT + tid], b2 = p2v[TT + tid]; int bi = p1i[TT + tid];
        float mm1, mm2; int ii1;
        if (bv < av || (bv == av && bi < ai)) { mm1 = bv; ii1 = bi; mm2 = fminf(av, b2); }
        else                                   { mm1 = av; ii1 = ai; mm2 = fminf(bv, a2); }
        bix[tid] = ii1;
        float margin = 3.0e-4f * sqrtf(x2s[tid] * e2m) + 1e-5f;
        if (tid < nt && (mm2 - mm1) <= margin) {
            int s = atomicAdd(&flg[0], 1);
            flg[1 + s] = tid;
        }
    }
    __syncthreads();

    // ---- exact fp32 fallback for flagged tokens (one warp per token) ----
    {
        int cnt = flg[0];
        const float* cbg = cbf + (size_t)g * KK * DD;
        for (int f = wid; f < cnt; f += 4) {
            int t = flg[1 + f];
            float x2 = x2s[t];
            float bv = INF; int bi = 0;
            for (int q = 0; q < KK / 32; ++q) {
                int k = q * 32 + lane;
                const float* row = cbg + (size_t)k * DD;
                float dot = 0.f;
                #pragma unroll
                for (int d = 0; d < DD; ++d)
                    dot = fmaf(xs[d * TT + t], __ldg(row + d), dot);
                float dist = (x2 - 2.0f * dot) + e2s[k];
                if (dist < bv) { bv = dist; bi = k; }
            }
            #pragma unroll
            for (int o = 16; o > 0; o >>= 1) {
                float ov = __shfl_xor_sync(0xffffffffu, bv, o);
                int oi = __shfl_xor_sync(0xffffffffu, bi, o);
                if (ov < bv || (ov == bv && oi < bi)) { bv = ov; bi = oi; }
            }
            if (lane == 0) bix[t] = bi;
        }
    }
    __syncthreads();

    // ---- gather winners (transpose-stage through xs) ----
    const float* cbg = cbf + (size_t)g * KK * DD;
    {
        const float* row = cbg + (size_t)bix[tid] * DD;
        #pragma unroll
        for (int q = 0; q < DD / 4; ++q) {
            float4 v = __ldg((const float4*)row + q);
            xs[(q * 4 + 0) * TT + tid] = v.x;
            xs[(q * 4 + 1) * TT + tid] = v.y;
            xs[(q * 4 + 2) * TT + tid] = v.z;
            xs[(q * 4 + 3) * TT + tid] = v.w;
        }
    }
    __syncthreads();

    // ---- coalesced writes (both output copies) ----
    float* out2 = out + (size_t)BB * CF * TS;
    const size_t obase = ((size_t)(b * CF + g * DD)) * TS + t0;
    if (nt == TT) {
        #pragma unroll
        for (int i = tid; i < DD * (TT / 4); i += NTH) {
            int dd = i >> 5, tq = i & 31;
            float4 v = *(const float4*)&xs[dd * TT + tq * 4];
            size_t o = obase + (size_t)dd * TS + tq * 4;
            *(float4*)(out + o) = v;
            if (two_copies) *(float4*)(out2 + o) = v;
        }
    } else {
        for (int i = tid; i < DD * TT; i += NTH) {
            int dd = i / TT, tt = i % TT;
            if (tt < nt) {
                float v = xs[dd * TT + tt];
                size_t o = obase + (size_t)dd * TS + tt;
                out[o] = v;
                if (two_copies) out2[o] = v;
            }
        }
    }
}

extern "C" void kernel_launch(void* const* d_in, const int* in_sizes, int n_in,
                              void* d_out, int out_size) {
    const float* x  = (const float*)d_in[0];
    const float* cb = (const float*)d_in[1];
    if (n_in >= 2 && in_sizes[0] == GG * KK * DD) {
        x = (const float*)d_in[1];
        cb = (const float*)d_in[0];
    }
    float* out = (float*)d_out;
    int two = (out_size >= 2 * BB * CF * TS) ? 1 : 0;

    cudaFuncSetAttribute(vq_main, cudaFuncAttributeMaxDynamicSharedMemorySize, SMEM_BYTES);

    prep_kernel<<<(GG * KK + PTH - 1) / PTH, PTH>>>(cb);
    vq_main<<<GG * BB * 32, NTH, SMEM_BYTES>>>(x, cb, out, two);
}

// round 6
// speedup vs baseline: 1.1659x; 1.1659x over previous
#include <cuda_runtime.h>
#include <cuda_bf16.h>
#include <cstdint>

#define GG   8
#define KK   1024
#define DD   64
#define BB   16
#define TS   4000
#define CF   512
#define TT   128        // tokens per CTA
#define NC   128        // codes per chunk
#define NCH  8
#define NTH  128
#define PTH  256

// ---------------- device globals ----------------
__device__ float g_e2[GG * KK];
__device__ unsigned int g_e2max[GG];
__device__ __align__(16) __nv_bfloat16 g_cbh[GG * KK * DD];
__device__ __align__(16) __nv_bfloat16 g_cbl[GG * KK * DD];

// ---------------- smem layout (bytes) ----------------
#define OFF_AH    0        // 16384: A hi bf16 SW128 (128 rows x 128B)
#define OFF_AL    16384    // 16384: A lo
#define OFF_B     32768    // 32768: x stage / B chunk (hi @ +0, lo @ +16384) / gather stage
#define OFF_E2S   65536    // 4096
#define OFF_X2S   69632    // 512
#define OFF_BIX   70144    // 512
#define OFF_P1V   70656    // 1024: [2][128] min1  (reused as fallback x scratch)
#define OFF_P1I   71680    // 1024
#define OFF_P2V   72704    // 1024
#define OFF_FLG   73728    // 520
#define SMEM_BYTES 74304

#define SW128(o) ((o) ^ (((o) >> 3) & 0x70))

__device__ __forceinline__ uint32_t smem_u32(const void* p) {
    uint32_t a;
    asm("{ .reg .u64 t; cvta.to.shared.u64 t, %1; cvt.u32.u64 %0, t; }" : "=r"(a) : "l"(p));
    return a;
}

#define LDMX4(r0, r1, r2, r3, a) \
    asm volatile("ldmatrix.sync.aligned.m8n8.x4.shared.b16 {%0,%1,%2,%3}, [%4];" \
        : "=r"(r0), "=r"(r1), "=r"(r2), "=r"(r3) : "r"(a))

#define MMA16816(c0, c1, c2, c3, a0, a1, a2, a3, b0, b1) \
    asm volatile("mma.sync.aligned.m16n8k16.row.col.f32.bf16.bf16.f32 " \
        "{%0,%1,%2,%3}, {%4,%5,%6,%7}, {%8,%9}, {%0,%1,%2,%3};" \
        : "+f"(c0), "+f"(c1), "+f"(c2), "+f"(c3) \
        : "r"(a0), "r"(a1), "r"(a2), "r"(a3), "r"(b0), "r"(b1))

#define CP_ASYNC16(dst, src) \
    asm volatile("cp.async.cg.shared.global [%0], [%1], 16;" :: "r"(dst), "l"(src) : "memory")
#define CP_COMMIT asm volatile("cp.async.commit_group;" ::: "memory")
#define CP_WAIT0  asm volatile("cp.async.wait_group 0;" ::: "memory")

// ---------------- prep: bf16 split codebook + e2 + e2max ----------------
__global__ void prep_kernel(const float* __restrict__ cb) {
    int r = blockIdx.x * blockDim.x + threadIdx.x;
    if (r < GG * KK) {
        const float* row = cb + (size_t)r * DD;
        float s = 0.f;
        #pragma unroll
        for (int d = 0; d < DD; ++d) {
            float v = row[d];
            s = fmaf(v, v, s);
            __nv_bfloat16 h = __float2bfloat16(v);
            g_cbh[(size_t)r * DD + d] = h;
            g_cbl[(size_t)r * DD + d] = __float2bfloat16(v - __bfloat162float(h));
        }
        g_e2[r] = s;
        atomicMax(&g_e2max[r / KK], __float_as_uint(s));
    }
}

__global__ __launch_bounds__(NTH, 3)
void vq_main(const float* __restrict__ x, const float* __restrict__ cbf,
             float* __restrict__ out, int two_copies) {
    extern __shared__ char smem[];
    const uint32_t base = smem_u32(smem);
    float* stg = (float*)(smem + OFF_B);     // staging: x tile, then B chunks, then gather
    float* e2s = (float*)(smem + OFF_E2S);
    float* x2s = (float*)(smem + OFF_X2S);
    int*   bix = (int*)  (smem + OFF_BIX);
    float* p1v = (float*)(smem + OFF_P1V);
    int*   p1i = (int*)  (smem + OFF_P1I);
    float* p2v = (float*)(smem + OFF_P2V);
    int*   flg = (int*)  (smem + OFF_FLG);

    const int tid = threadIdx.x;
    const int wid = tid >> 5;
    const int lane = tid & 31;

    const int tile = blockIdx.x & 31;
    const int b = (blockIdx.x >> 5) & 15;
    const int g = blockIdx.x >> 9;
    const int t0 = tile * TT;
    const int nt = min(TT, TS - t0);

    if (tid == 0) flg[0] = 0;

    // ---- stage x tile fp32 into the B region ([d][t] layout, zero-padded) ----
    const float* xb = x + ((size_t)(b * CF + g * DD)) * TS + t0;
    if (nt == TT) {
        #pragma unroll
        for (int i = tid; i < DD * (TT / 4); i += NTH) {
            int dd = i >> 5, tq = i & 31;
            float4 v = *(const float4*)(xb + (size_t)dd * TS + tq * 4);
            *(float4*)&stg[dd * TT + tq * 4] = v;
        }
    } else {
        for (int i = tid; i < DD * TT; i += NTH) {
            int dd = i / TT, tt = i % TT;
            stg[dd * TT + tt] = (tt < nt) ? xb[(size_t)dd * TS + tt] : 0.f;
        }
    }
    for (int i = tid; i < KK; i += NTH) e2s[i] = g_e2[g * KK + i];
    __syncthreads();

    // ---- build A hi/lo (SW128 rows of 128B) + x2; thread t = token t ----
    {
        float s = 0.f;
        #pragma unroll
        for (int q = 0; q < 8; ++q) {
            uint32_t hp[4], lp[4];
            #pragma unroll
            for (int pr = 0; pr < 4; ++pr) {
                float v0 = stg[(q * 8 + pr * 2) * TT + tid];
                float v1 = stg[(q * 8 + pr * 2 + 1) * TT + tid];
                s = fmaf(v0, v0, s);
                s = fmaf(v1, v1, s);
                __nv_bfloat16 h0 = __float2bfloat16(v0), h1 = __float2bfloat16(v1);
                __nv_bfloat16 l0 = __float2bfloat16(v0 - __bfloat162float(h0));
                __nv_bfloat16 l1 = __float2bfloat16(v1 - __bfloat162float(h1));
                hp[pr] = ((uint32_t)__bfloat16_as_ushort(h1) << 16) | __bfloat16_as_ushort(h0);
                lp[pr] = ((uint32_t)__bfloat16_as_ushort(l1) << 16) | __bfloat16_as_ushort(l0);
            }
            uint32_t off = SW128((uint32_t)(tid * 128 + q * 16));
            asm volatile("st.shared.v4.b32 [%0], {%1,%2,%3,%4};"
                :: "r"(base + OFF_AH + off), "r"(hp[0]), "r"(hp[1]), "r"(hp[2]), "r"(hp[3]) : "memory");
            asm volatile("st.shared.v4.b32 [%0], {%1,%2,%3,%4};"
                :: "r"(base + OFF_AL + off), "r"(lp[0]), "r"(lp[1]), "r"(lp[2]), "r"(lp[3]) : "memory");
        }
        x2s[tid] = s;
    }
    __syncthreads();   // A built; B region free for chunk loads

    // ---- warp tiling: 64 tokens x 64 codes per warp, 2 sub-passes of 32 codes ----
    const int m0 = (wid >> 1) * 64;       // token base
    const int n0 = (wid & 1) * 64;        // code half base within chunk
    const int half = wid & 1;
    const int gq = lane >> 2;             // 0..7
    const int t4 = lane & 3;              // 0..3

    const uint32_t aRow = (uint32_t)(m0 + (lane & 15));
    const uint32_t aCs = (uint32_t)(lane >> 4);
    const uint32_t bRowBase = (uint32_t)(n0 + (lane & 7) + ((lane >> 4) << 3));
    const uint32_t bCs = (uint32_t)((lane >> 3) & 1);

    uint32_t aB[4], aS[4];
    #pragma unroll
    for (int mt = 0; mt < 4; ++mt) {
        uint32_t r = aRow + 16u * mt;
        aB[mt] = base + OFF_AH + r * 128u;
        aS[mt] = r & 7u;
    }

    float x2r[4][2];
    #pragma unroll
    for (int mt = 0; mt < 4; ++mt) {
        x2r[mt][0] = x2s[m0 + 16 * mt + gq];
        x2r[mt][1] = x2s[m0 + 16 * mt + gq + 8];
    }

    const float INF = __int_as_float(0x7f800000);
    float m1[8], m2[8];
    int i1[8];
    #pragma unroll
    for (int r = 0; r < 8; ++r) { m1[r] = INF; m2[r] = INF; i1[r] = 0; }

    const char* cbh = (const char*)(g_cbh + (size_t)g * KK * DD);
    const char* cbl = (const char*)(g_cbl + (size_t)g * KK * DD);

    for (int c = 0; c < NCH; ++c) {
        // ---- cp.async B chunk hi/lo into SW128 smem ----
        {
            const char* srcH = cbh + (size_t)c * NC * DD * 2;
            const char* srcL = cbl + (size_t)c * NC * DD * 2;
            #pragma unroll
            for (int i = tid; i < 2048; i += NTH) {
                int hf = i >> 10, idx = i & 1023;
                const char* s = (hf ? srcL : srcH) + (size_t)idx * 16;
                uint32_t d = base + OFF_B + (uint32_t)hf * 16384u + SW128((uint32_t)(idx * 16));
                CP_ASYNC16(d, s);
            }
            CP_COMMIT;
            CP_WAIT0;
        }
        __syncthreads();

        #pragma unroll
        for (int nh = 0; nh < 2; ++nh) {
            uint32_t bB[2], bS[2];
            #pragma unroll
            for (int np = 0; np < 2; ++np) {
                uint32_t r = bRowBase + (uint32_t)(nh * 32) + 16u * np;
                bB[np] = base + OFF_B + r * 128u;
                bS[np] = r & 7u;
            }

            float acc[4][4][4];
            #pragma unroll
            for (int mt = 0; mt < 4; ++mt)
                #pragma unroll
                for (int ntl = 0; ntl < 4; ++ntl)
                    #pragma unroll
                    for (int f = 0; f < 4; ++f) acc[mt][ntl][f] = 0.f;

            #pragma unroll
            for (int p = 0; p < 3; ++p) {
                const uint32_t aOff = (p == 2) ? 16384u : 0u;   // A: hi,hi,lo
                const uint32_t bOff = (p == 1) ? 16384u : 0u;   // B: hi,lo,hi
                #pragma unroll
                for (int ks = 0; ks < 4; ++ks) {
                    uint32_t af[4][4];
                    #pragma unroll
                    for (int mt = 0; mt < 4; ++mt) {
                        uint32_t addr = aB[mt] + aOff + ((((uint32_t)(ks * 2) + aCs) ^ aS[mt]) << 4);
                        LDMX4(af[mt][0], af[mt][1], af[mt][2], af[mt][3], addr);
                    }
                    uint32_t bf[4][2];
                    #pragma unroll
                    for (int np = 0; np < 2; ++np) {
                        uint32_t addr = bB[np] + bOff + ((((uint32_t)(ks * 2) + bCs) ^ bS[np]) << 4);
                        LDMX4(bf[np * 2][0], bf[np * 2][1], bf[np * 2 + 1][0], bf[np * 2 + 1][1], addr);
                    }
                    #pragma unroll
                    for (int mt = 0; mt < 4; ++mt)
                        #pragma unroll
                        for (int ntl = 0; ntl < 4; ++ntl)
                            MMA16816(acc[mt][ntl][0], acc[mt][ntl][1], acc[mt][ntl][2], acc[mt][ntl][3],
                                     af[mt][0], af[mt][1], af[mt][2], af[mt][3],
                                     bf[ntl][0], bf[ntl][1]);
                }
            }

            // ---- argmin epilogue on register accumulators ----
            #pragma unroll
            for (int ntl = 0; ntl < 4; ++ntl) {
                int k = c * NC + n0 + nh * 32 + 8 * ntl + 2 * t4;
                float2 e2p = *(const float2*)&e2s[k];
                #pragma unroll
                for (int mt = 0; mt < 4; ++mt) {
                    float d00 = fmaf(acc[mt][ntl][0], -2.f, x2r[mt][0]) + e2p.x;
                    float d01 = fmaf(acc[mt][ntl][1], -2.f, x2r[mt][0]) + e2p.y;
                    float d10 = fmaf(acc[mt][ntl][2], -2.f, x2r[mt][1]) + e2p.x;
                    float d11 = fmaf(acc[mt][ntl][3], -2.f, x2r[mt][1]) + e2p.y;
                    int r0 = mt * 2, r1 = mt * 2 + 1;
                    if (d00 < m1[r0]) { m2[r0] = m1[r0]; m1[r0] = d00; i1[r0] = k; }
                    else if (d00 < m2[r0]) m2[r0] = d00;
                    if (d01 < m1[r0]) { m2[r0] = m1[r0]; m1[r0] = d01; i1[r0] = k + 1; }
                    else if (d01 < m2[r0]) m2[r0] = d01;
                    if (d10 < m1[r1]) { m2[r1] = m1[r1]; m1[r1] = d10; i1[r1] = k; }
                    else if (d10 < m2[r1]) m2[r1] = d10;
                    if (d11 < m1[r1]) { m2[r1] = m1[r1]; m1[r1] = d11; i1[r1] = k + 1; }
                    else if (d11 < m2[r1]) m2[r1] = d11;
                }
            }
        }
        __syncthreads();   // protect next chunk's cp.async writes
    }

    // ---- quad reduce (lanes t4=0..3 share each row) ----
    #pragma unroll
    for (int r = 0; r < 8; ++r) {
        #pragma unroll
        for (int o = 1; o <= 2; o <<= 1) {
            float om1 = __shfl_xor_sync(0xffffffffu, m1[r], o);
            float om2 = __shfl_xor_sync(0xffffffffu, m2[r], o);
            int   oi  = __shfl_xor_sync(0xffffffffu, i1[r], o);
            if (om1 < m1[r] || (om1 == m1[r] && oi < i1[r])) {
                m2[r] = fminf(m1[r], om2); m1[r] = om1; i1[r] = oi;
            } else {
                m2[r] = fminf(m2[r], om1);
            }
        }
    }

    // ---- stage per-code-half partials, merge across halves ----
    if (t4 == 0) {
        #pragma unroll
        for (int mt = 0; mt < 4; ++mt)
            #pragma unroll
            for (int h = 0; h < 2; ++h) {
                int r = mt * 2 + h;
                int tok = m0 + 16 * mt + 8 * h + gq;
                p1v[half * TT + tok] = m1[r];
                p1i[half * TT + tok] = i1[r];
                p2v[half * TT + tok] = m2[r];
            }
    }
    __syncthreads();

    const float e2m = __uint_as_float(g_e2max[g]);
    {
        float av = p1v[tid], a2 = p2v[tid]; int ai = p1i[tid];
        float bv = p1v[TT + tid], b2 = p2v[TT + tid]; int bi = p1i[TT + tid];
        float mm1, mm2; int ii1;
        if (bv < av || (bv == av && bi < ai)) { mm1 = bv; ii1 = bi; mm2 = fminf(av, b2); }
        else                                   { mm1 = av; ii1 = ai; mm2 = fminf(bv, a2); }
        bix[tid] = ii1;
        float margin = 3.0e-4f * sqrtf(x2s[tid] * e2m) + 1e-5f;
        if (tid < nt && (mm2 - mm1) <= margin) {
            int s = atomicAdd(&flg[0], 1);
            flg[1 + s] = tid;
        }
    }
    __syncthreads();

    // ---- exact fp32 fallback for flagged tokens (one warp per token) ----
    {
        int cnt = flg[0];
        const float* cbg = cbf + (size_t)g * KK * DD;
        float* xscr = p1v + wid * 64;   // per-warp 64-float scratch (p1v dead now)
        for (int f = wid; f < cnt; f += 4) {
            int t = flg[1 + f];
            // cooperative load of token t's 64 x-values from global
            xscr[lane]      = __ldg(xb + (size_t)lane * TS + t);
            xscr[lane + 32] = __ldg(xb + (size_t)(lane + 32) * TS + t);
            __syncwarp();
            float x2 = x2s[t];
            float bv = INF; int bi = 0;
            for (int q = 0; q < KK / 32; ++q) {
                int k = q * 32 + lane;
                const float* row = cbg + (size_t)k * DD;
                float dot = 0.f;
                #pragma unroll
                for (int d = 0; d < DD; ++d)
                    dot = fmaf(xscr[d], __ldg(row + d), dot);
                float dist = (x2 - 2.0f * dot) + e2s[k];
                if (dist < bv) { bv = dist; bi = k; }
            }
            #pragma unroll
            for (int o = 16; o > 0; o >>= 1) {
                float ov = __shfl_xor_sync(0xffffffffu, bv, o);
                int oi = __shfl_xor_sync(0xffffffffu, bi, o);
                if (ov < bv || (ov == bv && oi < bi)) { bv = ov; bi = oi; }
            }
            if (lane == 0) bix[t] = bi;
            __syncwarp();
        }
    }
    __syncthreads();

    // ---- gather winners (transpose-stage through B region) ----
    const float* cbg = cbf + (size_t)g * KK * DD;
    {
        const float* row = cbg + (size_t)bix[tid] * DD;
        #pragma unroll
        for (int q = 0; q < DD / 4; ++q) {
            float4 v = __ldg((const float4*)row + q);
            stg[(q * 4 + 0) * TT + tid] = v.x;
            stg[(q * 4 + 1) * TT + tid] = v.y;
            stg[(q * 4 + 2) * TT + tid] = v.z;
            stg[(q * 4 + 3) * TT + tid] = v.w;
        }
    }
    __syncthreads();

    // ---- coalesced writes (both output copies) ----
    float* out2 = out + (size_t)BB * CF * TS;
    const size_t obase = ((size_t)(b * CF + g * DD)) * TS + t0;
    if (nt == TT) {
        #pragma unroll
        for (int i = tid; i < DD * (TT / 4); i += NTH) {
            int dd = i >> 5, tq = i & 31;
            float4 v = *(const float4*)&stg[dd * TT + tq * 4];
            size_t o = obase + (size_t)dd * TS + tq * 4;
            *(float4*)(out + o) = v;
            if (two_copies) *(float4*)(out2 + o) = v;
        }
    } else {
        for (int i = tid; i < DD * TT; i += NTH) {
            int dd = i / TT, tt = i % TT;
            if (tt < nt) {
                float v = stg[dd * TT + tt];
                size_t o = obase + (size_t)dd * TS + tt;
                out[o] = v;
                if (two_copies) out2[o] = v;
            }
        }
    }
}

extern "C" void kernel_launch(void* const* d_in, const int* in_sizes, int n_in,
                              void* d_out, int out_size) {
    const float* x  = (const float*)d_in[0];
    const float* cb = (const float*)d_in[1];
    if (n_in >= 2 && in_sizes[0] == GG * KK * DD) {
        x = (const float*)d_in[1];
        cb = (const float*)d_in[0];
    }
    float* out = (float*)d_out;
    int two = (out_size >= 2 * BB * CF * TS) ? 1 : 0;

    cudaFuncSetAttribute(vq_main, cudaFuncAttributeMaxDynamicSharedMemorySize, SMEM_BYTES);

    prep_kernel<<<(GG * KK + PTH - 1) / PTH, PTH>>>(cb);
    vq_main<<<GG * BB * 32, NTH, SMEM_BYTES>>>(x, cb, out, two);
}

// round 8
// speedup vs baseline: 1.7449x; 1.4967x over previous
#include <cuda_runtime.h>
#include <cuda_bf16.h>
#include <cstdint>

#define GG   8
#define KK   1024
#define DD   64
#define BB   16
#define TS   4000
#define CF   512
#define TT   128        // tokens per CTA
#define NC   64         // codes per chunk
#define NCH  16
#define NTH  128
#define PTH  256

// ---------------- device globals ----------------
__device__ float g_e2[GG * KK];
__device__ unsigned int g_e2max[GG];
__device__ __align__(16) __nv_bfloat16 g_cbh[GG * KK * DD];
__device__ __align__(16) __nv_bfloat16 g_cbl[GG * KK * DD];

// ---------------- smem layout (bytes) ----------------
#define OFF_AH    0        // 16384: A hi bf16 SW128 (128 rows x 128B)
#define OFF_AL    16384    // 16384: A lo
#define OFF_B     32768    // 32768: x stage / 2 B bufs (each: hi 8K + lo 8K) / gather stage
#define OFF_E2S   65536    // 4096
#define OFF_X2S   69632    // 512
#define OFF_BIX   70144    // 512
#define OFF_P1V   70656    // 1024: [2][128] min1 (reused as fallback x scratch)
#define OFF_P1I   71680    // 1024
#define OFF_P2V   72704    // 1024
#define OFF_FLG   73728    // 520
#define SMEM_BYTES 74304

#define SW128(o) ((o) ^ (((o) >> 3) & 0x70))

__device__ __forceinline__ uint32_t smem_u32(const void* p) {
    uint32_t a;
    asm("{ .reg .u64 t; cvta.to.shared.u64 t, %1; cvt.u32.u64 %0, t; }" : "=r"(a) : "l"(p));
    return a;
}

#define LDMX4(r0, r1, r2, r3, a) \
    asm volatile("ldmatrix.sync.aligned.m8n8.x4.shared.b16 {%0,%1,%2,%3}, [%4];" \
        : "=r"(r0), "=r"(r1), "=r"(r2), "=r"(r3) : "r"(a))

#define MMA16816(c0, c1, c2, c3, a0, a1, a2, a3, b0, b1) \
    asm volatile("mma.sync.aligned.m16n8k16.row.col.f32.bf16.bf16.f32 " \
        "{%0,%1,%2,%3}, {%4,%5,%6,%7}, {%8,%9}, {%0,%1,%2,%3};" \
        : "+f"(c0), "+f"(c1), "+f"(c2), "+f"(c3) \
        : "r"(a0), "r"(a1), "r"(a2), "r"(a3), "r"(b0), "r"(b1))

#define CP_ASYNC16(dst, src) \
    asm volatile("cp.async.cg.shared.global [%0], [%1], 16;" :: "r"(dst), "l"(src) : "memory")
#define CP_COMMIT  asm volatile("cp.async.commit_group;" ::: "memory")
#define CP_WAIT(n) asm volatile("cp.async.wait_group %0;" :: "n"(n) : "memory")

// ---------------- prep: bf16 split codebook + e2 + e2max ----------------
__global__ void prep_kernel(const float* __restrict__ cb) {
    int r = blockIdx.x * blockDim.x + threadIdx.x;
    if (r < GG * KK) {
        const float* row = cb + (size_t)r * DD;
        float s = 0.f;
        #pragma unroll
        for (int d = 0; d < DD; ++d) {
            float v = row[d];
            s = fmaf(v, v, s);
            __nv_bfloat16 h = __float2bfloat16(v);
            g_cbh[(size_t)r * DD + d] = h;
            g_cbl[(size_t)r * DD + d] = __float2bfloat16(v - __bfloat162float(h));
        }
        g_e2[r] = s;
        atomicMax(&g_e2max[r / KK], __float_as_uint(s));
    }
}

__global__ __launch_bounds__(NTH, 3)
void vq_main(const float* __restrict__ x, const float* __restrict__ cbf,
             float* __restrict__ out, int two_copies) {
    extern __shared__ char smem[];
    const uint32_t base = smem_u32(smem);
    float* stg = (float*)(smem + OFF_B);
    float* e2s = (float*)(smem + OFF_E2S);
    float* x2s = (float*)(smem + OFF_X2S);
    int*   bix = (int*)  (smem + OFF_BIX);
    float* p1v = (float*)(smem + OFF_P1V);
    int*   p1i = (int*)  (smem + OFF_P1I);
    float* p2v = (float*)(smem + OFF_P2V);
    int*   flg = (int*)  (smem + OFF_FLG);

    const int tid = threadIdx.x;
    const int wid = tid >> 5;
    const int lane = tid & 31;

    const int tile = blockIdx.x & 31;
    const int b = (blockIdx.x >> 5) & 15;
    const int g = blockIdx.x >> 9;
    const int t0 = tile * TT;
    const int nt = min(TT, TS - t0);

    if (tid == 0) flg[0] = 0;

    // ---- stage x tile fp32 into the B region ([d][t], zero-padded) ----
    const float* xb = x + ((size_t)(b * CF + g * DD)) * TS + t0;
    if (nt == TT) {
        #pragma unroll
        for (int i = tid; i < DD * (TT / 4); i += NTH) {
            int dd = i >> 5, tq = i & 31;
            float4 v = *(const float4*)(xb + (size_t)dd * TS + tq * 4);
            *(float4*)&stg[dd * TT + tq * 4] = v;
        }
    } else {
        for (int i = tid; i < DD * TT; i += NTH) {
            int dd = i / TT, tt = i % TT;
            stg[dd * TT + tt] = (tt < nt) ? xb[(size_t)dd * TS + tt] : 0.f;
        }
    }
    for (int i = tid; i < KK; i += NTH) e2s[i] = g_e2[g * KK + i];
    __syncthreads();

    // ---- build A hi/lo (SW128 rows of 128B) + x2; thread t = token t ----
    {
        float s = 0.f;
        #pragma unroll
        for (int q = 0; q < 8; ++q) {
            uint32_t hp[4], lp[4];
            #pragma unroll
            for (int pr = 0; pr < 4; ++pr) {
                float v0 = stg[(q * 8 + pr * 2) * TT + tid];
                float v1 = stg[(q * 8 + pr * 2 + 1) * TT + tid];
                s = fmaf(v0, v0, s);
                s = fmaf(v1, v1, s);
                __nv_bfloat16 h0 = __float2bfloat16(v0), h1 = __float2bfloat16(v1);
                __nv_bfloat16 l0 = __float2bfloat16(v0 - __bfloat162float(h0));
                __nv_bfloat16 l1 = __float2bfloat16(v1 - __bfloat162float(h1));
                hp[pr] = ((uint32_t)__bfloat16_as_ushort(h1) << 16) | __bfloat16_as_ushort(h0);
                lp[pr] = ((uint32_t)__bfloat16_as_ushort(l1) << 16) | __bfloat16_as_ushort(l0);
            }
            uint32_t off = SW128((uint32_t)(tid * 128 + q * 16));
            asm volatile("st.shared.v4.b32 [%0], {%1,%2,%3,%4};"
                :: "r"(base + OFF_AH + off), "r"(hp[0]), "r"(hp[1]), "r"(hp[2]), "r"(hp[3]) : "memory");
            asm volatile("st.shared.v4.b32 [%0], {%1,%2,%3,%4};"
                :: "r"(base + OFF_AL + off), "r"(lp[0]), "r"(lp[1]), "r"(lp[2]), "r"(lp[3]) : "memory");
        }
        x2s[tid] = s;
    }
    __syncthreads();   // A built; B region free

    // ---- warp tiling: 64 tokens x 32 codes per warp ----
    const int m0 = (wid >> 1) * 64;       // token base
    const int n0 = (wid & 1) * 32;        // code half base within 64-chunk
    const int half = wid & 1;
    const int gq = lane >> 2;             // 0..7
    const int t4 = lane & 3;              // 0..3

    const uint32_t aRow = (uint32_t)(m0 + (lane & 15));
    const uint32_t aCs = (uint32_t)(lane >> 4);
    const uint32_t bRowBase = (uint32_t)(n0 + (lane & 7) + ((lane >> 4) << 3));
    const uint32_t bCs = (uint32_t)((lane >> 3) & 1);

    uint32_t aB[4], aS[4];
    #pragma unroll
    for (int mt = 0; mt < 4; ++mt) {
        uint32_t r = aRow + 16u * mt;
        aB[mt] = base + OFF_AH + r * 128u;
        aS[mt] = r & 7u;
    }
    uint32_t bRo[2], bSh[2];
    #pragma unroll
    for (int np = 0; np < 2; ++np) {
        uint32_t r = bRowBase + 16u * np;
        bRo[np] = r * 128u;
        bSh[np] = r & 7u;
    }

    const float INF = __int_as_float(0x7f800000);
    float m1[8], m2[8];
    int i1[8];
    #pragma unroll
    for (int r = 0; r < 8; ++r) { m1[r] = INF; m2[r] = INF; i1[r] = 0; }

    const char* cbh = (const char*)(g_cbh + (size_t)g * KK * DD);
    const char* cbl = (const char*)(g_cbl + (size_t)g * KK * DD);

    // prefetch chunk 0
    {
        #pragma unroll
        for (int i = tid; i < 1024; i += NTH) {
            int hf = i >> 9, idx = i & 511;
            const char* s = (hf ? cbl : cbh) + (size_t)idx * 16;
            uint32_t d = base + OFF_B + (uint32_t)hf * 8192u + SW128((uint32_t)(idx * 16));
            CP_ASYNC16(d, s);
        }
        CP_COMMIT;
    }

    for (int c = 0; c < NCH; ++c) {
        __syncthreads();   // chunk c-1 fully consumed (buffer (c+1)&1 free)
        if (c + 1 < NCH) {
            const char* srcH = cbh + (size_t)(c + 1) * NC * DD * 2;
            const char* srcL = cbl + (size_t)(c + 1) * NC * DD * 2;
            uint32_t bb = base + OFF_B + (uint32_t)((c + 1) & 1) * 16384u;
            #pragma unroll
            for (int i = tid; i < 1024; i += NTH) {
                int hf = i >> 9, idx = i & 511;
                const char* s = (hf ? srcL : srcH) + (size_t)idx * 16;
                uint32_t d = bb + (uint32_t)hf * 8192u + SW128((uint32_t)(idx * 16));
                CP_ASYNC16(d, s);
            }
            CP_COMMIT;
            CP_WAIT(1);    // chunk c arrived
        } else {
            CP_WAIT(0);
        }
        __syncthreads();   // chunk c visible CTA-wide

        const uint32_t bufB = base + OFF_B + (uint32_t)(c & 1) * 16384u;

        float acc[4][4][4];
        #pragma unroll
        for (int mt = 0; mt < 4; ++mt)
            #pragma unroll
            for (int ntl = 0; ntl < 4; ++ntl)
                #pragma unroll
                for (int f = 0; f < 4; ++f) acc[mt][ntl][f] = 0.f;

        #pragma unroll
        for (int ks = 0; ks < 4; ++ks) {
            const uint32_t kcol = (uint32_t)(ks * 2);
            uint32_t bh[4][2], bl[4][2];
            #pragma unroll
            for (int np = 0; np < 2; ++np) {
                uint32_t co = ((kcol + bCs) ^ bSh[np]) << 4;
                LDMX4(bh[np * 2][0], bh[np * 2][1], bh[np * 2 + 1][0], bh[np * 2 + 1][1],
                      bufB + bRo[np] + co);
                LDMX4(bl[np * 2][0], bl[np * 2][1], bl[np * 2 + 1][0], bl[np * 2 + 1][1],
                      bufB + 8192u + bRo[np] + co);
            }
            uint32_t af[4][4];
            #pragma unroll
            for (int mt = 0; mt < 4; ++mt) {
                uint32_t addr = aB[mt] + (((kcol + aCs) ^ aS[mt]) << 4);
                LDMX4(af[mt][0], af[mt][1], af[mt][2], af[mt][3], addr);
            }
            #pragma unroll
            for (int mt = 0; mt < 4; ++mt)
                #pragma unroll
                for (int ntl = 0; ntl < 4; ++ntl)
                    MMA16816(acc[mt][ntl][0], acc[mt][ntl][1], acc[mt][ntl][2], acc[mt][ntl][3],
                             af[mt][0], af[mt][1], af[mt][2], af[mt][3],
                             bh[ntl][0], bh[ntl][1]);
            #pragma unroll
            for (int mt = 0; mt < 4; ++mt)
                #pragma unroll
                for (int ntl = 0; ntl < 4; ++ntl)
                    MMA16816(acc[mt][ntl][0], acc[mt][ntl][1], acc[mt][ntl][2], acc[mt][ntl][3],
                             af[mt][0], af[mt][1], af[mt][2], af[mt][3],
                             bl[ntl][0], bl[ntl][1]);
            #pragma unroll
            for (int mt = 0; mt < 4; ++mt) {
                uint32_t addr = aB[mt] + 16384u + (((kcol + aCs) ^ aS[mt]) << 4);
                LDMX4(af[mt][0], af[mt][1], af[mt][2], af[mt][3], addr);
            }
            #pragma unroll
            for (int mt = 0; mt < 4; ++mt)
                #pragma unroll
                for (int ntl = 0; ntl < 4; ++ntl)
                    MMA16816(acc[mt][ntl][0], acc[mt][ntl][1], acc[mt][ntl][2], acc[mt][ntl][3],
                             af[mt][0], af[mt][1], af[mt][2], af[mt][3],
                             bh[ntl][0], bh[ntl][1]);
        }

        // ---- argmin epilogue: dist' = e2 - 2*dot (x2 dropped; gap-invariant) ----
        #pragma unroll
        for (int ntl = 0; ntl < 4; ++ntl) {
            int k = c * NC + n0 + 8 * ntl + 2 * t4;
            float2 e2p = *(const float2*)&e2s[k];
            #pragma unroll
            for (int mt = 0; mt < 4; ++mt) {
                float d00 = fmaf(acc[mt][ntl][0], -2.f, e2p.x);
                float d01 = fmaf(acc[mt][ntl][1], -2.f, e2p.y);
                float d10 = fmaf(acc[mt][ntl][2], -2.f, e2p.x);
                float d11 = fmaf(acc[mt][ntl][3], -2.f, e2p.y);
                int r0 = mt * 2, r1 = mt * 2 + 1;
                m2[r0] = fminf(m2[r0], fmaxf(d00, m1[r0]));
                i1[r0] = (d00 < m1[r0]) ? k : i1[r0];
                m1[r0] = fminf(m1[r0], d00);
                m2[r0] = fminf(m2[r0], fmaxf(d01, m1[r0]));
                i1[r0] = (d01 < m1[r0]) ? (k + 1) : i1[r0];
                m1[r0] = fminf(m1[r0], d01);
                m2[r1] = fminf(m2[r1], fmaxf(d10, m1[r1]));
                i1[r1] = (d10 < m1[r1]) ? k : i1[r1];
                m1[r1] = fminf(m1[r1], d10);
                m2[r1] = fminf(m2[r1], fmaxf(d11, m1[r1]));
                i1[r1] = (d11 < m1[r1]) ? (k + 1) : i1[r1];
                m1[r1] = fminf(m1[r1], d11);
            }
        }
    }

    // ---- quad reduce (lanes t4=0..3 share each row) ----
    #pragma unroll
    for (int r = 0; r < 8; ++r) {
        #pragma unroll
        for (int o = 1; o <= 2; o <<= 1) {
            float om1 = __shfl_xor_sync(0xffffffffu, m1[r], o);
            float om2 = __shfl_xor_sync(0xffffffffu, m2[r], o);
            int   oi  = __shfl_xor_sync(0xffffffffu, i1[r], o);
            if (om1 < m1[r] || (om1 == m1[r] && oi < i1[r])) {
                m2[r] = fminf(m1[r], om2); m1[r] = om1; i1[r] = oi;
            } else {
                m2[r] = fminf(m2[r], om1);
            }
        }
    }

    // ---- stage per-code-half partials, merge across halves ----
    if (t4 == 0) {
        #pragma unroll
        for (int mt = 0; mt < 4; ++mt)
            #pragma unroll
            for (int h = 0; h < 2; ++h) {
                int r = mt * 2 + h;
                int tok = m0 + 16 * mt + 8 * h + gq;
                p1v[half * TT + tok] = m1[r];
                p1i[half * TT + tok] = i1[r];
                p2v[half * TT + tok] = m2[r];
            }
    }
    __syncthreads();

    const float e2m = __uint_as_float(g_e2max[g]);
    {
        float av = p1v[tid], a2 = p2v[tid]; int ai = p1i[tid];
        float bv = p1v[TT + tid], b2 = p2v[TT + tid]; int bi = p1i[TT + tid];
        float mm1, mm2; int ii1;
        if (bv < av || (bv == av && bi < ai)) { mm1 = bv; ii1 = bi; mm2 = fminf(av, b2); }
        else                                   { mm1 = av; ii1 = ai; mm2 = fminf(bv, a2); }
        bix[tid] = ii1;
        float margin = 3.0e-4f * sqrtf(x2s[tid] * e2m) + 1e-5f;
        if (tid < nt && (mm2 - mm1) <= margin) {
            int s = atomicAdd(&flg[0], 1);
            flg[1 + s] = tid;
        }
    }
    __syncthreads();

    // ---- exact fp32 fallback: MUST mirror reference arithmetic (x2 - 2*dot) + e2 ----
    {
        int cnt = flg[0];
        const float* cbg = cbf + (size_t)g * KK * DD;
        float* xscr = p1v + wid * 64;
        for (int f = wid; f < cnt; f += 4) {
            int t = flg[1 + f];
            xscr[lane]      = __ldg(xb + (size_t)lane * TS + t);
            xscr[lane + 32] = __ldg(xb + (size_t)(lane + 32) * TS + t);
            __syncwarp();
            float x2 = x2s[t];
            float bv = INF; int bi = 0;
            for (int q = 0; q < KK / 32; ++q) {
                int k = q * 32 + lane;
                const float* row = cbg + (size_t)k * DD;
                float dot = 0.f;
                #pragma unroll
                for (int d = 0; d < DD; ++d)
                    dot = fmaf(xscr[d], __ldg(row + d), dot);
                float dist = (x2 - 2.0f * dot) + e2s[k];
                if (dist < bv) { bv = dist; bi = k; }
            }
            #pragma unroll
            for (int o = 16; o > 0; o >>= 1) {
                float ov = __shfl_xor_sync(0xffffffffu, bv, o);
                int oi = __shfl_xor_sync(0xffffffffu, bi, o);
                if (ov < bv || (ov == bv && oi < bi)) { bv = ov; bi = oi; }
            }
            if (lane == 0) bix[t] = bi;
            __syncwarp();
        }
    }
    __syncthreads();

    // ---- gather winners (transpose-stage through B region) ----
    const float* cbg = cbf + (size_t)g * KK * DD;
    {
        const float* row = cbg + (size_t)bix[tid] * DD;
        #pragma unroll
        for (int q = 0; q < DD / 4; ++q) {
            float4 v = __ldg((const float4*)row + q);
            stg[(q * 4 + 0) * TT + tid] = v.x;
            stg[(q * 4 + 1) * TT + tid] = v.y;
            stg[(q * 4 + 2) * TT + tid] = v.z;
            stg[(q * 4 + 3) * TT + tid] = v.w;
        }
    }
    __syncthreads();

    // ---- coalesced writes (both output copies) ----
    float* out2 = out + (size_t)BB * CF * TS;
    const size_t obase = ((size_t)(b * CF + g * DD)) * TS + t0;
    if (nt == TT) {
        #pragma unroll
        for (int i = tid; i < DD * (TT / 4); i += NTH) {
            int dd = i >> 5, tq = i & 31;
            float4 v = *(const float4*)&stg[dd * TT + tq * 4];
            size_t o = obase + (size_t)dd * TS + tq * 4;
            *(float4*)(out + o) = v;
            if (two_copies) *(float4*)(out2 + o) = v;
        }
    } else {
        for (int i = tid; i < DD * TT; i += NTH) {
            int dd = i / TT, tt = i % TT;
            if (tt < nt) {
                float v = stg[dd * TT + tt];
                size_t o = obase + (size_t)dd * TS + tt;
                out[o] = v;
                if (two_copies) out2[o] = v;
            }
        }
    }
}

extern "C" void kernel_launch(void* const* d_in, const int* in_sizes, int n_in,
                              void* d_out, int out_size) {
    const float* x  = (const float*)d_in[0];
    const float* cb = (const float*)d_in[1];
    if (n_in >= 2 && in_sizes[0] == GG * KK * DD) {
        x = (const float*)d_in[1];
        cb = (const float*)d_in[0];
    }
    float* out = (float*)d_out;
    int two = (out_size >= 2 * BB * CF * TS) ? 1 : 0;

    cudaFuncSetAttribute(vq_main, cudaFuncAttributeMaxDynamicSharedMemorySize, SMEM_BYTES);

    prep_kernel<<<(GG * KK + PTH - 1) / PTH, PTH>>>(cb);
    vq_main<<<GG * BB * 32, NTH, SMEM_BYTES>>>(x, cb, out, two);
}